// round 17
// baseline (speedup 1.0000x reference)
#include <cuda_runtime.h>
#include <cuda_fp16.h>
#include <math.h>
#include <stdint.h>

#define TOK    8192      // B*S
#define DM     1024
#define S_LEN  2048
#define NH     16
#define DK     64
#define QKV_N  3072
#define KP     2048      // K' = 2*1024 (fp16 hi/lo split folded into K)

// ---------------------------------------------------------------------------
// Static device scratch
// ---------------------------------------------------------------------------
__device__ __half g_x2   [(size_t)TOK   * KP];   // x split: [hi | lo]
__device__ __half g_attn2[(size_t)TOK   * KP];   // attn out split: [hi | lo]
__device__ __half g_w2qkv[(size_t)QKV_N * KP];   // W_qkv^T: [hi | hi]
__device__ __half g_w2out[(size_t)DM    * KP];   // W_out^T: [hi | hi]
// attention operands, per (b,h) contiguous:
__device__ __half g_q2 [(size_t)4 * NH * S_LEN * 128];  // [bh][s][hi(64)|lo(64)]
__device__ __half g_khi[(size_t)4 * NH * S_LEN * 64];   // K hi plane only
__device__ __half g_vhi[(size_t)4 * NH * S_LEN * 64];   // V hi plane only

// ---------------------------------------------------------------------------
// PTX helpers (baseline ISA: ldmatrix / mma.sync / cp.async — valid on sm_103)
// ---------------------------------------------------------------------------
__device__ __forceinline__ uint32_t smem_u32(const void* p) {
    uint32_t a;
    asm("{ .reg .u64 t; cvta.to.shared.u64 t, %1; cvt.u32.u64 %0, t; }"
        : "=r"(a) : "l"(p));
    return a;
}

__device__ __forceinline__ void cp_async16(uint32_t saddr, const void* gaddr) {
    asm volatile("cp.async.cg.shared.global [%0], [%1], 16;"
                 :: "r"(saddr), "l"(gaddr) : "memory");
}

__device__ __forceinline__ void ldmatrix_x4(uint32_t* r, uint32_t addr) {
    asm volatile("ldmatrix.sync.aligned.m8n8.x4.shared.b16 {%0,%1,%2,%3}, [%4];"
                 : "=r"(r[0]), "=r"(r[1]), "=r"(r[2]), "=r"(r[3]) : "r"(addr));
}

__device__ __forceinline__ void ldmatrix_x4_trans(uint32_t* r, uint32_t addr) {
    asm volatile("ldmatrix.sync.aligned.m8n8.x4.trans.shared.b16 {%0,%1,%2,%3}, [%4];"
                 : "=r"(r[0]), "=r"(r[1]), "=r"(r[2]), "=r"(r[3]) : "r"(addr));
}

__device__ __forceinline__ void mma_f16(float* c, const uint32_t* a,
                                        uint32_t b0, uint32_t b1) {
    asm volatile(
        "mma.sync.aligned.m16n8k16.row.col.f32.f16.f16.f32 "
        "{%0,%1,%2,%3}, {%4,%5,%6,%7}, {%8,%9}, {%0,%1,%2,%3};"
        : "+f"(c[0]), "+f"(c[1]), "+f"(c[2]), "+f"(c[3])
        : "r"(a[0]), "r"(a[1]), "r"(a[2]), "r"(a[3]), "r"(b0), "r"(b1));
}

__device__ __forceinline__ void split2h(float x, float y,
                                        __half2& hh, __half2& ll) {
    __half h0 = __float2half_rn(x);
    __half h1 = __float2half_rn(y);
    __half l0 = __float2half_rn(x - __half2float(h0));
    __half l1 = __float2half_rn(y - __half2float(h1));
    hh = __halves2half2(h0, h1);
    ll = __halves2half2(l0, l1);
}

__device__ __forceinline__ void pack_hilo(float x, float y,
                                          uint32_t& hh, uint32_t& ll) {
    __half2 H, L;
    split2h(x, y, H, L);
    hh = *reinterpret_cast<uint32_t*>(&H);
    ll = *reinterpret_cast<uint32_t*>(&L);
}

// ---------------------------------------------------------------------------
// Conversion kernels: fp32 -> fp16 hi/lo split
// ---------------------------------------------------------------------------
__global__ __launch_bounds__(256) void convert_x_kernel(
    const float* __restrict__ x, __half* __restrict__ x2)
{
    size_t i = (size_t)blockIdx.x * 256 + threadIdx.x;
    size_t e = i * 2;
    size_t row = e >> 10;
    int col = (int)(e & 1023);
    float2 v = *(const float2*)(x + row * DM + col);
    __half2 hh, ll;
    split2h(v.x, v.y, hh, ll);
    __half* base = x2 + row * KP + col;
    *(__half2*)(base)        = hh;
    *(__half2*)(base + 1024) = ll;
}

__global__ __launch_bounds__(256) void convert_w_kernel(
    const float* __restrict__ W,       // [1024][N] row-major
    __half* __restrict__ Wt,           // [N][KP]
    int N)
{
    __shared__ float tile[32][33];
    const int n0 = blockIdx.x * 32, k0 = blockIdx.y * 32;
    const int tx = threadIdx.x, ty = threadIdx.y;
    #pragma unroll
    for (int r = ty; r < 32; r += 8)
        tile[r][tx] = W[(size_t)(k0 + r) * N + n0 + tx];
    __syncthreads();
    #pragma unroll
    for (int r = ty; r < 32; r += 8) {
        int n = n0 + r, k = k0 + tx;
        __half hi = __float2half_rn(tile[tx][r]);
        __half* p = Wt + (size_t)n * KP + k;
        p[0]    = hi;
        p[1024] = hi;
    }
}

// ---------------------------------------------------------------------------
// HMMA GEMM: 128x256 CTA tile, 8 warps (2x4), warp tile 64x64, BK=32,
// m16n8k16, 2-stage cp.async, single sync per chunk. Dynamic smem.
// ---------------------------------------------------------------------------
#define BM       128
#define BN       256
#define BKC      32
#define NKCHUNK  (KP / BKC)             // 64
#define ROW_PAD  40
#define A_STG    (BM * ROW_PAD * 2)     // 10240
#define B_STG    (BN * ROW_PAD * 2)     // 20480
#define B_OFF    (2 * A_STG)            // 20480
#define GEMM_SMEM (2 * A_STG + 2 * B_STG)   // 61440

struct GemmCtx {
    float acc[4][8][4];
    int gr, gc;
};

__device__ __forceinline__ void hmma_mainloop(
    const __half* __restrict__ A,
    const __half* __restrict__ Bt,
    uint32_t sb, GemmCtx& ctx)
{
    const int tid  = threadIdx.x;
    const int lane = tid & 31, wid = tid >> 5;
    const int warp_m = wid & 1;        // 0..1 -> 64-row slab
    const int warp_n = wid >> 1;       // 0..3 -> 64-col slab
    const int m0 = blockIdx.y * BM, n0 = blockIdx.x * BN;

    const __half* Ab = A  + (size_t)m0 * KP;
    const __half* Bb = Bt + (size_t)n0 * KP;

    const uint32_t a_base = sb
        + (uint32_t)((warp_m * 64 + (lane & 15)) * (ROW_PAD * 2))
        + (uint32_t)((lane >> 4) * 16);
    const uint32_t b_base = sb + B_OFF
        + (uint32_t)((warp_n * 64 + (lane & 7) + ((lane >> 4) & 1) * 8) * (ROW_PAD * 2))
        + (uint32_t)(((lane >> 3) & 1) * 16);

    #pragma unroll
    for (int mt = 0; mt < 4; mt++)
        #pragma unroll
        for (int nt = 0; nt < 8; nt++)
            #pragma unroll
            for (int q = 0; q < 4; q++) ctx.acc[mt][nt][q] = 0.0f;

    auto load_stage = [&](int stage, int k0) {
        #pragma unroll
        for (int i = 0; i < 2; i++) {           // A: 512 chunks, 2/thread
            int chunk = tid + i * 256;
            int row = chunk >> 2, c4 = chunk & 3;
            cp_async16(sb + (uint32_t)(stage * A_STG + row * (ROW_PAD * 2) + c4 * 16),
                       Ab + (size_t)row * KP + k0 + c4 * 8);
        }
        #pragma unroll
        for (int i = 0; i < 4; i++) {           // B: 1024 chunks, 4/thread
            int chunk = tid + i * 256;
            int row = chunk >> 2, c4 = chunk & 3;
            cp_async16(sb + (uint32_t)(B_OFF + stage * B_STG + row * (ROW_PAD * 2) + c4 * 16),
                       Bb + (size_t)row * KP + k0 + c4 * 8);
        }
        asm volatile("cp.async.commit_group;" ::: "memory");
    };

    load_stage(0, 0);

    for (int kc = 0; kc < NKCHUNK; kc++) {
        const int cur = kc & 1;
        asm volatile("cp.async.wait_group 0;" ::: "memory");
        __syncthreads();
        if (kc + 1 < NKCHUNK) load_stage(cur ^ 1, (kc + 1) * BKC);

        const uint32_t aoff = a_base + cur * A_STG;
        const uint32_t boff = b_base + cur * B_STG;
        #pragma unroll
        for (int ks = 0; ks < 2; ks++) {
            uint32_t a[4][4];
            #pragma unroll
            for (int mt = 0; mt < 4; mt++)
                ldmatrix_x4(a[mt], aoff + mt * 16 * (ROW_PAD * 2) + ks * 32);
            uint32_t b[4][4];
            #pragma unroll
            for (int np = 0; np < 4; np++)
                ldmatrix_x4(b[np], boff + np * 16 * (ROW_PAD * 2) + ks * 32);
            #pragma unroll
            for (int mt = 0; mt < 4; mt++)
                #pragma unroll
                for (int nt = 0; nt < 8; nt++)
                    mma_f16(ctx.acc[mt][nt], a[mt],
                            b[nt >> 1][(nt & 1) * 2 + 0],
                            b[nt >> 1][(nt & 1) * 2 + 1]);
        }
    }

    ctx.gr = m0 + warp_m * 64 + (lane >> 2);
    ctx.gc = n0 + warp_n * 64 + (lane & 3) * 2;
}

__global__ __launch_bounds__(256, 1) void hmma_gemm_kernel(
    const __half* __restrict__ A,
    const __half* __restrict__ Bt,
    const float* __restrict__ bias,
    float* __restrict__ C, int Nc)
{
    extern __shared__ char gs[];
    GemmCtx ctx;
    hmma_mainloop(A, Bt, smem_u32(gs), ctx);

    #pragma unroll
    for (int mt = 0; mt < 4; mt++) {
        #pragma unroll
        for (int nt = 0; nt < 8; nt++) {
            int col = ctx.gc + nt * 8;
            float2 bv = *(const float2*)(bias + col);
            int r0 = ctx.gr + mt * 16;
            float2 o0 = { ctx.acc[mt][nt][0] + bv.x, ctx.acc[mt][nt][1] + bv.y };
            float2 o1 = { ctx.acc[mt][nt][2] + bv.x, ctx.acc[mt][nt][3] + bv.y };
            *(float2*)(C + (size_t)r0 * Nc + col)       = o0;
            *(float2*)(C + (size_t)(r0 + 8) * Nc + col) = o1;
        }
    }
}

// QKV variant: writes pre-split attention operands q2/khi/vhi
__global__ __launch_bounds__(256, 1) void hmma_gemm_qkv_kernel(
    const __half* __restrict__ A,
    const __half* __restrict__ Bt,
    const float* __restrict__ bias,
    __half* __restrict__ q2, __half* __restrict__ khi,
    __half* __restrict__ vhi)
{
    extern __shared__ char gs[];
    GemmCtx ctx;
    hmma_mainloop(A, Bt, smem_u32(gs), ctx);

    #pragma unroll
    for (int mt = 0; mt < 4; mt++) {
        #pragma unroll
        for (int rr = 0; rr < 2; rr++) {
            int r  = ctx.gr + mt * 16 + rr * 8;
            int bb = r >> 11, ss = r & 2047;
            #pragma unroll
            for (int nt = 0; nt < 8; nt++) {
                int col = ctx.gc + nt * 8;
                float2 bv = *(const float2*)(bias + col);
                float x = ctx.acc[mt][nt][rr * 2 + 0] + bv.x;
                float y = ctx.acc[mt][nt][rr * 2 + 1] + bv.y;
                __half2 hh, ll;
                split2h(x, y, hh, ll);
                int sec = col >> 10;
                int h = (col & 1023) >> 6, d = col & 63;
                if (sec == 0) {                 // Q: [hi | lo]
                    size_t base = ((size_t)(bb * NH + h) * S_LEN + ss) * 128 + d;
                    *(__half2*)(q2 + base)      = hh;
                    *(__half2*)(q2 + base + 64) = ll;
                } else {
                    size_t base = ((size_t)(bb * NH + h) * S_LEN + ss) * 64 + d;
                    if (sec == 1) *(__half2*)(khi + base) = hh;
                    else          *(__half2*)(vhi + base) = hh;
                }
            }
        }
    }
}

// ---------------------------------------------------------------------------
// Flash attention: FA2-style register softmax, fp16 2-term splits.
// (unchanged from R16 — validated)
// ---------------------------------------------------------------------------
#define AQ_STR 136
#define KV_STR 72
#define K_STG  (64 * KV_STR * 2)
#define AOFF_Q 0
#define AOFF_K (128 * AQ_STR * 2)
#define AOFF_V (AOFF_K + 2 * K_STG)
#define AOFF_B (AOFF_V + 2 * K_STG)
#define ATTN_SMEM_BYTES (AOFF_B + 2 * 256 * 4)

__global__ __launch_bounds__(256) void attn_mma_kernel(
    const float* __restrict__ rel_bias, __half* __restrict__ attn2)
{
    extern __shared__ char smraw[];
    const uint32_t sQ = smem_u32(smraw + AOFF_Q);
    const uint32_t sK = smem_u32(smraw + AOFF_K);
    const uint32_t sV = smem_u32(smraw + AOFF_V);
    float* bias_s = (float*)(smraw + AOFF_B);

    const int tid  = threadIdx.x;
    const int lane = tid & 31, w = tid >> 5;

    const int q0 = blockIdx.x * 128;
    const int h  = blockIdx.y;
    const int b  = blockIdx.z;
    const int bh = b * NH + h;
    const int t0 = b * S_LEN + q0;

    const __half* qg = g_q2  + ((size_t)bh * S_LEN + q0) * 128;
    const __half* kg = g_khi + (size_t)bh * S_LEN * 64;
    const __half* vg = g_vhi + (size_t)bh * S_LEN * 64;

    auto load_tile = [&](int stg, int j0) {
        #pragma unroll
        for (int it = 0; it < 2; it++) {
            int c = tid + it * 256;
            int row = c >> 3, u = c & 7;
            cp_async16(sK + (uint32_t)(stg * K_STG + row * (KV_STR * 2) + u * 16),
                       kg + (size_t)(j0 + row) * 64 + u * 8);
        }
        #pragma unroll
        for (int it = 0; it < 2; it++) {
            int c = tid + it * 256;
            int row = c >> 3, u = c & 7;
            cp_async16(sV + (uint32_t)(stg * K_STG + row * (KV_STR * 2) + u * 16),
                       vg + (size_t)(j0 + row) * 64 + u * 8);
        }
        if (tid < 191) {
            int rel = (q0 - j0) + (tid - 63) + 1024;
            rel = min(max(rel, 0), 2 * 1024);
            bias_s[stg * 256 + tid] = __ldg(rel_bias + rel * NH + h);
        }
        asm volatile("cp.async.commit_group;" ::: "memory");
    };

    #pragma unroll
    for (int it = 0; it < 8; it++) {
        int c = tid + it * 256;
        int row = c >> 4, u = c & 15;
        cp_async16(sQ + (uint32_t)(row * (AQ_STR * 2) + u * 16),
                   qg + (size_t)row * 128 + u * 8);
    }
    load_tile(0, 0);

    const uint32_t aQ = sQ + (uint32_t)((w * 16 + (lane & 15)) * (AQ_STR * 2)
                                        + (lane >> 4) * 16);
    const uint32_t bK = sK + (uint32_t)((((lane & 7) + ((lane >> 4) & 1) * 8) * (KV_STR * 2))
                                        + ((lane >> 3) & 1) * 16);
    const uint32_t bV = sV + (uint32_t)((lane & 15) * (KV_STR * 2) + (lane >> 4) * 16);

    float o[8][4];
    #pragma unroll
    for (int nt = 0; nt < 8; nt++)
        #pragma unroll
        for (int q = 0; q < 4; q++) o[nt][q] = 0.0f;

    float mA = -1e30f, mB = -1e30f, lA = 0.0f, lB = 0.0f;
    const int r0  = lane >> 2;
    const int c0q = (lane & 3) * 2;
    const int rA  = w * 16 + r0, rB = rA + 8;

    for (int j = 0; j < S_LEN / 64; j++) {
        const int s = j & 1;
        asm volatile("cp.async.wait_group 0;" ::: "memory");
        __syncthreads();
        if (j + 1 < S_LEN / 64) load_tile(s ^ 1, (j + 1) * 64);

        const uint32_t kb = bK + s * K_STG;
        const uint32_t vb = bV + s * K_STG;
        const float* bs = bias_s + s * 256;

        float sf[8][4];
        #pragma unroll
        for (int nt = 0; nt < 8; nt++)
            #pragma unroll
            for (int q = 0; q < 4; q++) sf[nt][q] = 0.0f;
        #pragma unroll
        for (int kt = 0; kt < 4; kt++) {
            uint32_t aH[4], aL[4];
            ldmatrix_x4(aH, aQ + kt * 32);
            ldmatrix_x4(aL, aQ + 128 + kt * 32);
            #pragma unroll
            for (int np = 0; np < 4; np++) {
                uint32_t bf[4];
                ldmatrix_x4(bf, kb + np * 16 * (KV_STR * 2) + kt * 32);
                mma_f16(sf[np * 2 + 0], aH, bf[0], bf[1]);
                mma_f16(sf[np * 2 + 1], aH, bf[2], bf[3]);
                mma_f16(sf[np * 2 + 0], aL, bf[0], bf[1]);
                mma_f16(sf[np * 2 + 1], aL, bf[2], bf[3]);
            }
        }

        float mlA = -1e30f, mlB = -1e30f;
        #pragma unroll
        for (int nt = 0; nt < 8; nt++) {
            int c = nt * 8 + c0q;
            sf[nt][0] = fmaf(sf[nt][0], 0.125f, bs[rA - c + 63]);
            sf[nt][1] = fmaf(sf[nt][1], 0.125f, bs[rA - c + 62]);
            sf[nt][2] = fmaf(sf[nt][2], 0.125f, bs[rB - c + 63]);
            sf[nt][3] = fmaf(sf[nt][3], 0.125f, bs[rB - c + 62]);
            mlA = fmaxf(mlA, fmaxf(sf[nt][0], sf[nt][1]));
            mlB = fmaxf(mlB, fmaxf(sf[nt][2], sf[nt][3]));
        }
        mlA = fmaxf(mlA, __shfl_xor_sync(0xffffffffu, mlA, 1));
        mlA = fmaxf(mlA, __shfl_xor_sync(0xffffffffu, mlA, 2));
        mlB = fmaxf(mlB, __shfl_xor_sync(0xffffffffu, mlB, 1));
        mlB = fmaxf(mlB, __shfl_xor_sync(0xffffffffu, mlB, 2));

        float mnA = fmaxf(mA, mlA), mnB = fmaxf(mB, mlB);
        float escA = __expf(mA - mnA), escB = __expf(mB - mnB);
        float rsA = 0.0f, rsB = 0.0f;
        #pragma unroll
        for (int nt = 0; nt < 8; nt++) {
            sf[nt][0] = __expf(sf[nt][0] - mnA);
            sf[nt][1] = __expf(sf[nt][1] - mnA);
            sf[nt][2] = __expf(sf[nt][2] - mnB);
            sf[nt][3] = __expf(sf[nt][3] - mnB);
            rsA += sf[nt][0] + sf[nt][1];
            rsB += sf[nt][2] + sf[nt][3];
        }
        rsA += __shfl_xor_sync(0xffffffffu, rsA, 1);
        rsA += __shfl_xor_sync(0xffffffffu, rsA, 2);
        rsB += __shfl_xor_sync(0xffffffffu, rsB, 1);
        rsB += __shfl_xor_sync(0xffffffffu, rsB, 2);
        lA = lA * escA + rsA; mA = mnA;
        lB = lB * escB + rsB; mB = mnB;

        #pragma unroll
        for (int nt = 0; nt < 8; nt++) {
            o[nt][0] *= escA; o[nt][1] *= escA;
            o[nt][2] *= escB; o[nt][3] *= escB;
        }

        #pragma unroll
        for (int kt = 0; kt < 4; kt++) {
            uint32_t aH[4], aL[4];
            pack_hilo(sf[2 * kt][0],     sf[2 * kt][1],     aH[0], aL[0]);
            pack_hilo(sf[2 * kt][2],     sf[2 * kt][3],     aH[1], aL[1]);
            pack_hilo(sf[2 * kt + 1][0], sf[2 * kt + 1][1], aH[2], aL[2]);
            pack_hilo(sf[2 * kt + 1][2], sf[2 * kt + 1][3], aH[3], aL[3]);
            #pragma unroll
            for (int np = 0; np < 4; np++) {
                uint32_t bf[4];
                ldmatrix_x4_trans(bf, vb + kt * 16 * (KV_STR * 2) + np * 32);
                mma_f16(o[np * 2 + 0], aH, bf[0], bf[1]);
                mma_f16(o[np * 2 + 1], aH, bf[2], bf[3]);
                mma_f16(o[np * 2 + 0], aL, bf[0], bf[1]);
                mma_f16(o[np * 2 + 1], aL, bf[2], bf[3]);
            }
        }
    }

    {
        const float iA = 1.0f / lA, iB = 1.0f / lB;
        const int tokA = t0 + rA, tokB = t0 + rB;
        const int colb = h * DK + c0q;
        #pragma unroll
        for (int nt = 0; nt < 8; nt++) {
            int col = colb + nt * 8;
            {
                __half2 hh, ll;
                split2h(o[nt][0] * iA, o[nt][1] * iA, hh, ll);
                __half* p = attn2 + (size_t)tokA * KP + col;
                *(__half2*)(p)        = hh;
                *(__half2*)(p + 1024) = ll;
            }
            {
                __half2 hh, ll;
                split2h(o[nt][2] * iB, o[nt][3] * iB, hh, ll);
                __half* p = attn2 + (size_t)tokB * KP + col;
                *(__half2*)(p)        = hh;
                *(__half2*)(p + 1024) = ll;
            }
        }
    }
}

// ---------------------------------------------------------------------------
// Launch
// ---------------------------------------------------------------------------
extern "C" void kernel_launch(void* const* d_in, const int* in_sizes, int n_in,
                              void* d_out, int out_size)
{
    const float* x        = (const float*)d_in[0];
    const float* W_qkv    = (const float*)d_in[1];
    const float* b_qkv    = (const float*)d_in[2];
    const float* W_out    = (const float*)d_in[3];
    const float* b_out    = (const float*)d_in[4];
    const float* rel_bias = (const float*)d_in[5];
    float* out = (float*)d_out;

    __half *x2p, *a2p, *wqp, *wop, *q2p, *khp, *vhp;
    cudaGetSymbolAddress((void**)&x2p, g_x2);
    cudaGetSymbolAddress((void**)&a2p, g_attn2);
    cudaGetSymbolAddress((void**)&wqp, g_w2qkv);
    cudaGetSymbolAddress((void**)&wop, g_w2out);
    cudaGetSymbolAddress((void**)&q2p, g_q2);
    cudaGetSymbolAddress((void**)&khp, g_khi);
    cudaGetSymbolAddress((void**)&vhp, g_vhi);

    cudaFuncSetAttribute(attn_mma_kernel,
                         cudaFuncAttributeMaxDynamicSharedMemorySize,
                         ATTN_SMEM_BYTES);
    cudaFuncSetAttribute(hmma_gemm_kernel,
                         cudaFuncAttributeMaxDynamicSharedMemorySize,
                         GEMM_SMEM);
    cudaFuncSetAttribute(hmma_gemm_qkv_kernel,
                         cudaFuncAttributeMaxDynamicSharedMemorySize,
                         GEMM_SMEM);

    // 0) Conversions
    convert_x_kernel<<<TOK * DM / 512, 256>>>(x, x2p);
    {
        dim3 wb(32, 8);
        convert_w_kernel<<<dim3(QKV_N / 32, DM / 32), wb>>>(W_qkv, wqp, QKV_N);
        convert_w_kernel<<<dim3(DM / 32, DM / 32),   wb>>>(W_out, wop, DM);
    }

    // 1) QKV projection -> pre-split attention operands
    {
        dim3 grid(QKV_N / BN, TOK / BM);
        hmma_gemm_qkv_kernel<<<grid, 256, GEMM_SMEM>>>(x2p, wqp, b_qkv,
                                                       q2p, khp, vhp);
    }
    // 2) Attention (FA2-style HMMA, register softmax), writes split fp16
    {
        dim3 grid(S_LEN / 128, NH, 4);
        attn_mma_kernel<<<grid, 256, ATTN_SMEM_BYTES>>>(rel_bias, a2p);
    }
    // 3) Output projection -> d_out
    {
        dim3 grid(DM / BN, TOK / BM);
        hmma_gemm_kernel<<<grid, 256, GEMM_SMEM>>>(a2p, wop, b_out, out, DM);
    }
}